// round 1
// baseline (speedup 1.0000x reference)
#include <cuda_runtime.h>
#include <math.h>
#include <stdint.h>

#define N_NODES   100000
#define N_EDGES   3200000
#define NE_TOT    (N_EDGES + N_NODES)   // edges + self loops
#define IN_C      256
#define OUT_C     64
#define NEG_SLOPE 0.2f

// ---------------- scratch (static device globals; no allocation) ----------------
__device__ float g_h[(size_t)N_NODES * OUT_C];   // 25.6 MB: h = x @ W^T
__device__ float g_si[N_NODES];                  // h @ a_i
__device__ float g_sj[N_NODES];                  // h @ a_j
__device__ float g_m[N_NODES];                   // segment max
__device__ float g_den[N_NODES];                 // segment sum of exp -> reciprocal
__device__ float g_e[NE_TOT];                    // per-edge e, then exp(e - m)

// ---------------- helpers ----------------
__device__ __forceinline__ void atomicMaxF(float* addr, float v) {
    // Monotonic bit trick: positive floats compare as signed ints,
    // negative floats compare reversed as unsigned ints. Init must be -inf.
    if (v >= 0.0f) atomicMax((int*)addr, __float_as_int(v));
    else           atomicMin((unsigned int*)addr, __float_as_uint(v));
}

// ---------------- kernel 0: init ----------------
__global__ void init_kernel(float* __restrict__ out) {
    int i = blockIdx.x * blockDim.x + threadIdx.x;
    if (i < N_NODES * OUT_C) out[i] = 0.0f;
    if (i < N_NODES) {
        g_m[i]   = -INFINITY;
        g_den[i] = 0.0f;
    }
}

// ---------------- kernel 1: SGEMM  h[n][c] = sum_k x[n][k] * W[c][k] ----------------
// 64x64 tile per block, BK=32, 256 threads, 4x4 register tile per thread.
__global__ __launch_bounds__(256) void gemm_kernel(const float* __restrict__ x,
                                                   const float* __restrict__ W) {
    __shared__ float As[32][68];   // As[k][m], pad 68 keeps 16B alignment per row
    __shared__ float Bs[32][68];   // Bs[k][n] = W[n][k]

    const int tid = threadIdx.x;
    const int m0  = blockIdx.x * 64;
    const int tx  = tid & 15;     // n-tile
    const int ty  = tid >> 4;     // m-tile
    const int lm  = tid >> 3;            // 0..31 row for loads
    const int lk  = (tid & 7) << 2;      // 0,4,...,28 k-offset for float4 loads

    float acc[4][4];
#pragma unroll
    for (int i = 0; i < 4; i++)
#pragma unroll
        for (int j = 0; j < 4; j++) acc[i][j] = 0.0f;

    for (int k0 = 0; k0 < IN_C; k0 += 32) {
#pragma unroll
        for (int half = 0; half < 2; half++) {
            int m  = lm + half * 32;
            int gm = m0 + m;
            float4 v = make_float4(0.f, 0.f, 0.f, 0.f);
            if (gm < N_NODES)
                v = *(const float4*)(x + (size_t)gm * IN_C + k0 + lk);
            As[lk + 0][m] = v.x; As[lk + 1][m] = v.y;
            As[lk + 2][m] = v.z; As[lk + 3][m] = v.w;

            int n = lm + half * 32;   // OUT_C = 64 rows of W
            float4 w = *(const float4*)(W + (size_t)n * IN_C + k0 + lk);
            Bs[lk + 0][n] = w.x; Bs[lk + 1][n] = w.y;
            Bs[lk + 2][n] = w.z; Bs[lk + 3][n] = w.w;
        }
        __syncthreads();

#pragma unroll
        for (int k = 0; k < 32; k++) {
            float4 av = *(const float4*)&As[k][ty * 4];
            float4 bv = *(const float4*)&Bs[k][tx * 4];
            float a_[4] = {av.x, av.y, av.z, av.w};
            float b_[4] = {bv.x, bv.y, bv.z, bv.w};
#pragma unroll
            for (int i = 0; i < 4; i++)
#pragma unroll
                for (int j = 0; j < 4; j++)
                    acc[i][j] += a_[i] * b_[j];
        }
        __syncthreads();
    }

#pragma unroll
    for (int i = 0; i < 4; i++) {
        int gm = m0 + ty * 4 + i;
        if (gm < N_NODES) {
            float4 v = make_float4(acc[i][0], acc[i][1], acc[i][2], acc[i][3]);
            *(float4*)(g_h + (size_t)gm * OUT_C + tx * 4) = v;
        }
    }
}

// ---------------- kernel 2: attention scores per node ----------------
__global__ void scores_kernel(const float* __restrict__ a) {
    __shared__ float sa[2 * OUT_C];
    if (threadIdx.x < 2 * OUT_C) sa[threadIdx.x] = a[threadIdx.x];
    __syncthreads();

    int i = blockIdx.x * blockDim.x + threadIdx.x;
    if (i >= N_NODES) return;
    const float4* hp = (const float4*)(g_h + (size_t)i * OUT_C);
    float si = 0.f, sj = 0.f;
#pragma unroll
    for (int q = 0; q < 16; q++) {
        float4 h4 = hp[q];
        si += h4.x * sa[q * 4 + 0] + h4.y * sa[q * 4 + 1]
            + h4.z * sa[q * 4 + 2] + h4.w * sa[q * 4 + 3];
        sj += h4.x * sa[OUT_C + q * 4 + 0] + h4.y * sa[OUT_C + q * 4 + 1]
            + h4.z * sa[OUT_C + q * 4 + 2] + h4.w * sa[OUT_C + q * 4 + 3];
    }
    g_si[i] = si;
    g_sj[i] = sj;
}

// ---------------- kernel 3: e = leaky_relu(s_i[col] + s_j[row]); segment max ----------------
__global__ void edge_max_kernel(const int* __restrict__ ei) {
    int i = blockIdx.x * blockDim.x + threadIdx.x;
    if (i >= NE_TOT) return;
    int r, c;
    if (i < N_EDGES) { r = ei[i]; c = ei[N_EDGES + i]; }
    else             { r = c = i - N_EDGES; }
    float e = g_si[c] + g_sj[r];
    e = (e >= 0.f) ? e : NEG_SLOPE * e;
    g_e[i] = e;
    atomicMaxF(&g_m[c], e);
}

// ---------------- kernel 4: ex = exp(e - m[col]); segment sum ----------------
__global__ void edge_exp_kernel(const int* __restrict__ ei) {
    int i = blockIdx.x * blockDim.x + threadIdx.x;
    if (i >= NE_TOT) return;
    int c;
    if (i < N_EDGES) c = ei[N_EDGES + i];
    else             c = i - N_EDGES;
    float ex = expf(g_e[i] - g_m[c]);
    g_e[i] = ex;
    atomicAdd(&g_den[c], ex);
}

// ---------------- kernel 5: reciprocal denom ----------------
__global__ void inv_kernel() {
    int i = blockIdx.x * blockDim.x + threadIdx.x;
    if (i < N_NODES) g_den[i] = 1.0f / g_den[i];
}

// ---------------- kernel 6: out[col] += alpha * h[row]  (16 threads / edge) ----------------
__global__ void scatter_kernel(const int* __restrict__ ei, float* __restrict__ out) {
    long long g = (long long)blockIdx.x * blockDim.x + threadIdx.x;
    int e = (int)(g >> 4);
    if (e >= NE_TOT) return;
    int l = ((int)g) & 15;   // channel group: 4 floats each

    int r, c;
    if (e < N_EDGES) { r = ei[e]; c = ei[N_EDGES + e]; }
    else             { r = c = e - N_EDGES; }

    float alpha = g_e[e] * g_den[c];
    float4 hv = *(const float4*)(g_h + (size_t)r * OUT_C + l * 4);
    float* p = out + (size_t)c * OUT_C + l * 4;
    asm volatile("red.global.add.v4.f32 [%0], {%1, %2, %3, %4};"
                 :: "l"(p),
                    "f"(alpha * hv.x), "f"(alpha * hv.y),
                    "f"(alpha * hv.z), "f"(alpha * hv.w)
                 : "memory");
}

// ---------------- launch ----------------
extern "C" void kernel_launch(void* const* d_in, const int* in_sizes, int n_in,
                              void* d_out, int out_size) {
    const float* x  = (const float*)d_in[0];
    const int*   ei = (const int*)  d_in[1];
    const float* W  = (const float*)d_in[2];
    const float* a  = (const float*)d_in[3];
    float* out = (float*)d_out;

    init_kernel<<<(N_NODES * OUT_C + 255) / 256, 256>>>(out);
    gemm_kernel<<<(N_NODES + 63) / 64, 256>>>(x, W);
    scores_kernel<<<(N_NODES + 255) / 256, 256>>>(a);
    edge_max_kernel<<<(NE_TOT + 255) / 256, 256>>>(ei);
    edge_exp_kernel<<<(NE_TOT + 255) / 256, 256>>>(ei);
    inv_kernel<<<(N_NODES + 255) / 256, 256>>>();
    long long scatter_threads = (long long)NE_TOT * 16;
    scatter_kernel<<<(unsigned)((scatter_threads + 255) / 256), 256>>>(ei, out);
}

// round 2
// speedup vs baseline: 1.4624x; 1.4624x over previous
#include <cuda_runtime.h>
#include <math.h>
#include <stdint.h>

#define N_NODES   100000
#define N_EDGES   3200000
#define NE_TOT    (N_EDGES + N_NODES)   // edges + self loops
#define IN_C      256
#define OUT_C     64
#define NEG_SLOPE 0.2f

#define SCAN_BS   1024
#define SCAN_NB   ((N_NODES + SCAN_BS - 1) / SCAN_BS)   // 98

// ---------------- scratch (static device globals; no allocation) ----------------
__device__ float  g_h[(size_t)N_NODES * OUT_C];   // 25.6 MB: h = x @ W^T
__device__ float  g_si[N_NODES];                  // h @ a_i
__device__ float  g_sj[N_NODES];                  // h @ a_j
__device__ int    g_cnt[N_NODES];                 // histogram by col
__device__ int    g_start[N_NODES + 1];           // CSR offsets
__device__ int    g_cur[N_NODES];                 // placement cursors
__device__ int    g_bsum[SCAN_NB];                // block sums for scan
__device__ float2 g_csr[NE_TOT];                  // {row (bitcast), p = exp(e)}

// ---------------- kernel: zero histogram ----------------
__global__ void zero_kernel() {
    int i = blockIdx.x * blockDim.x + threadIdx.x;
    if (i < N_NODES) g_cnt[i] = 0;
}

// ---------------- kernel: SGEMM  h[n][c] = sum_k x[n][k] * W[c][k] ----------------
__global__ __launch_bounds__(256) void gemm_kernel(const float* __restrict__ x,
                                                   const float* __restrict__ W) {
    __shared__ float As[32][68];
    __shared__ float Bs[32][68];

    const int tid = threadIdx.x;
    const int m0  = blockIdx.x * 64;
    const int tx  = tid & 15;
    const int ty  = tid >> 4;
    const int lm  = tid >> 3;
    const int lk  = (tid & 7) << 2;

    float acc[4][4];
#pragma unroll
    for (int i = 0; i < 4; i++)
#pragma unroll
        for (int j = 0; j < 4; j++) acc[i][j] = 0.0f;

    for (int k0 = 0; k0 < IN_C; k0 += 32) {
#pragma unroll
        for (int half = 0; half < 2; half++) {
            int m  = lm + half * 32;
            int gm = m0 + m;
            float4 v = make_float4(0.f, 0.f, 0.f, 0.f);
            if (gm < N_NODES)
                v = *(const float4*)(x + (size_t)gm * IN_C + k0 + lk);
            As[lk + 0][m] = v.x; As[lk + 1][m] = v.y;
            As[lk + 2][m] = v.z; As[lk + 3][m] = v.w;

            int n = lm + half * 32;
            float4 w = *(const float4*)(W + (size_t)n * IN_C + k0 + lk);
            Bs[lk + 0][n] = w.x; Bs[lk + 1][n] = w.y;
            Bs[lk + 2][n] = w.z; Bs[lk + 3][n] = w.w;
        }
        __syncthreads();

#pragma unroll
        for (int k = 0; k < 32; k++) {
            float4 av = *(const float4*)&As[k][ty * 4];
            float4 bv = *(const float4*)&Bs[k][tx * 4];
            float a_[4] = {av.x, av.y, av.z, av.w};
            float b_[4] = {bv.x, bv.y, bv.z, bv.w};
#pragma unroll
            for (int i = 0; i < 4; i++)
#pragma unroll
                for (int j = 0; j < 4; j++)
                    acc[i][j] += a_[i] * b_[j];
        }
        __syncthreads();
    }

#pragma unroll
    for (int i = 0; i < 4; i++) {
        int gm = m0 + ty * 4 + i;
        if (gm < N_NODES) {
            float4 v = make_float4(acc[i][0], acc[i][1], acc[i][2], acc[i][3]);
            *(float4*)(g_h + (size_t)gm * OUT_C + tx * 4) = v;
        }
    }
}

// ---------------- kernel: per-node attention scores ----------------
__global__ void scores_kernel(const float* __restrict__ a) {
    __shared__ float sa[2 * OUT_C];
    if (threadIdx.x < 2 * OUT_C) sa[threadIdx.x] = a[threadIdx.x];
    __syncthreads();

    int i = blockIdx.x * blockDim.x + threadIdx.x;
    if (i >= N_NODES) return;
    const float4* hp = (const float4*)(g_h + (size_t)i * OUT_C);
    float si = 0.f, sj = 0.f;
#pragma unroll
    for (int q = 0; q < 16; q++) {
        float4 h4 = hp[q];
        si += h4.x * sa[q * 4 + 0] + h4.y * sa[q * 4 + 1]
            + h4.z * sa[q * 4 + 2] + h4.w * sa[q * 4 + 3];
        sj += h4.x * sa[OUT_C + q * 4 + 0] + h4.y * sa[OUT_C + q * 4 + 1]
            + h4.z * sa[OUT_C + q * 4 + 2] + h4.w * sa[OUT_C + q * 4 + 3];
    }
    g_si[i] = si;
    g_sj[i] = sj;
}

// ---------------- kernel: histogram of destinations ----------------
__global__ void hist_kernel(const int* __restrict__ ei) {
    int i = blockIdx.x * blockDim.x + threadIdx.x;
    if (i >= NE_TOT) return;
    int c = (i < N_EDGES) ? ei[N_EDGES + i] : (i - N_EDGES);
    atomicAdd(&g_cnt[c], 1);
}

// ---------------- scan: counts -> exclusive offsets ----------------
__global__ __launch_bounds__(SCAN_BS) void scan1_kernel() {
    __shared__ int sd[SCAN_BS];
    int tid = threadIdx.x;
    int i   = blockIdx.x * SCAN_BS + tid;
    int v   = (i < N_NODES) ? g_cnt[i] : 0;
    sd[tid] = v;
    __syncthreads();
#pragma unroll
    for (int off = 1; off < SCAN_BS; off <<= 1) {
        int t = (tid >= off) ? sd[tid - off] : 0;
        __syncthreads();
        sd[tid] += t;
        __syncthreads();
    }
    if (i < N_NODES) g_start[i] = sd[tid] - v;       // exclusive within block
    if (tid == SCAN_BS - 1) g_bsum[blockIdx.x] = sd[tid];
}

__global__ void scan2_kernel() {
    __shared__ int sb[SCAN_NB];
    int tid = threadIdx.x;
    if (tid < SCAN_NB) sb[tid] = g_bsum[tid];
    __syncthreads();
    if (tid == 0) {
        int run = 0;
        for (int b = 0; b < SCAN_NB; b++) { int t = sb[b]; sb[b] = run; run += t; }
    }
    __syncthreads();
    if (tid < SCAN_NB) g_bsum[tid] = sb[tid];
}

__global__ void scan3_kernel() {
    int i = blockIdx.x * blockDim.x + threadIdx.x;
    if (i < N_NODES) {
        int s = g_start[i] + g_bsum[i >> 10];
        g_start[i] = s;
        g_cur[i]   = s;
        if (i == 0) g_start[N_NODES] = NE_TOT;
    }
}

// ---------------- kernel: placement — build CSR entries {row, p} ----------------
__global__ void place_kernel(const int* __restrict__ ei) {
    int i = blockIdx.x * blockDim.x + threadIdx.x;
    if (i >= NE_TOT) return;
    int r, c;
    if (i < N_EDGES) { r = ei[i]; c = ei[N_EDGES + i]; }
    else             { r = c = i - N_EDGES; }
    float e = g_si[c] + g_sj[r];
    e = (e >= 0.f) ? e : NEG_SLOPE * e;
    float p = expf(e);                        // shift-free softmax weight; bounded
    int pos = atomicAdd(&g_cur[c], 1);
    g_csr[pos] = make_float2(__int_as_float(r), p);
}

// ---------------- kernel: warp-per-node fused softmax + aggregate ----------------
__global__ __launch_bounds__(256) void gather_kernel(float* __restrict__ out) {
    int warp = (int)((blockIdx.x * 256 + threadIdx.x) >> 5);
    int lane = threadIdx.x & 31;
    if (warp >= N_NODES) return;

    int s = g_start[warp];
    int e = g_start[warp + 1];

    float acc0 = 0.f, acc1 = 0.f, sp = 0.f;
#pragma unroll 4
    for (int k = s; k < e; k++) {
        float2 t = g_csr[k];                  // broadcast within warp
        int   r  = __float_as_int(t.x);
        float p  = t.y;
        sp += p;
        float2 h2 = *(const float2*)(g_h + ((size_t)r << 6) + (lane << 1));
        acc0 = fmaf(p, h2.x, acc0);
        acc1 = fmaf(p, h2.y, acc1);
    }
    float inv = 1.0f / sp;                    // sp > 0: self-loop always present
    float2 o = make_float2(acc0 * inv, acc1 * inv);
    *(float2*)(out + ((size_t)warp << 6) + (lane << 1)) = o;
}

// ---------------- launch ----------------
extern "C" void kernel_launch(void* const* d_in, const int* in_sizes, int n_in,
                              void* d_out, int out_size) {
    const float* x  = (const float*)d_in[0];
    const int*   ei = (const int*)  d_in[1];
    const float* W  = (const float*)d_in[2];
    const float* a  = (const float*)d_in[3];
    float* out = (float*)d_out;

    zero_kernel<<<(N_NODES + 255) / 256, 256>>>();
    gemm_kernel<<<(N_NODES + 63) / 64, 256>>>(x, W);
    scores_kernel<<<(N_NODES + 255) / 256, 256>>>(a);
    hist_kernel<<<(NE_TOT + 255) / 256, 256>>>(ei);
    scan1_kernel<<<SCAN_NB, SCAN_BS>>>();
    scan2_kernel<<<1, 128>>>();
    scan3_kernel<<<(N_NODES + 255) / 256, 256>>>();
    place_kernel<<<(NE_TOT + 255) / 256, 256>>>(ei);
    long long gthreads = (long long)N_NODES * 32;
    gather_kernel<<<(unsigned)((gthreads + 255) / 256), 256>>>(out);
}

// round 4
// speedup vs baseline: 1.5718x; 1.0748x over previous
#include <cuda_runtime.h>
#include <math.h>
#include <stdint.h>

#define N_NODES   100000
#define N_EDGES   3200000
#define NE_TOT    (N_EDGES + N_NODES)   // edges + self loops
#define IN_C      256
#define OUT_C     64
#define NEG_SLOPE 0.2f

#define SCAN_BS   1024
#define SCAN_NB   ((N_NODES + SCAN_BS - 1) / SCAN_BS)   // 98

// ---------------- scratch (static device globals; no allocation) ----------------
__device__ float  g_h[(size_t)N_NODES * OUT_C];   // 25.6 MB: h = x @ W^T
__device__ float  g_si[N_NODES];                  // h @ a_i
__device__ float  g_sj[N_NODES];                  // h @ a_j
__device__ int    g_cnt[N_NODES];                 // histogram by col
__device__ int    g_start[N_NODES + 1];           // CSR offsets
__device__ int    g_cur[N_NODES];                 // placement cursors
__device__ int    g_bsum[SCAN_NB];                // block sums for scan
__device__ float2 g_csr[NE_TOT];                  // {row (bitcast), p = exp(e)}

// ---------------- helpers ----------------
__device__ __forceinline__ uint32_t f2tf(float x) {
    uint32_t r;
    asm("cvt.rna.tf32.f32 %0, %1;" : "=r"(r) : "f"(x));
    return r;
}
__device__ __forceinline__ float uaf(uint32_t u) { return __uint_as_float(u); }

__device__ __forceinline__ void mma_tf32(float* d, const uint32_t* a, const uint32_t* b) {
    asm volatile(
        "mma.sync.aligned.m16n8k8.row.col.f32.tf32.tf32.f32 "
        "{%0,%1,%2,%3}, {%4,%5,%6,%7}, {%8,%9}, {%0,%1,%2,%3};"
        : "+f"(d[0]), "+f"(d[1]), "+f"(d[2]), "+f"(d[3])
        : "r"(a[0]), "r"(a[1]), "r"(a[2]), "r"(a[3]), "r"(b[0]), "r"(b[1]));
}

// ---------------- kernel: init (self-loop pre-counted in histogram) ----------------
__global__ void zero_kernel() {
    int i = blockIdx.x * blockDim.x + threadIdx.x;
    if (i < N_NODES) g_cnt[i] = 1;
}

// ---------------- kernel: tensor-core GEMM (3xTF32) + fused scores ----------------
// Block = 256 thr = 8 warps. Each warp: 16 rows x 64 cols. Block tile: 128 rows.
__global__ __launch_bounds__(256) void gemm_tc_kernel(const float* __restrict__ x,
                                                      const float* __restrict__ W,
                                                      const float* __restrict__ a) {
    __shared__ float Bs[64 * 68];   // W[:, kchunk] as [n][k], stride 68 (conflict-free)
    __shared__ float sa[2 * OUT_C];

    const int tid  = threadIdx.x;
    const int warp = tid >> 5;
    const int lane = tid & 31;
    const int qrow = lane >> 2;     // 0..7
    const int qcol = lane & 3;      // 0..3

    if (tid < 2 * OUT_C) sa[tid] = a[tid];
    __syncthreads();                // sa visible before anyone proceeds

    const int row0 = blockIdx.x * 128 + warp * 16 + qrow;
    const int row1 = row0 + 8;
    const bool v0 = row0 < N_NODES;
    const bool v1 = row1 < N_NODES;
    const float* p0 = x + (size_t)(v0 ? row0 : 0) * IN_C + qcol;
    const float* p1 = x + (size_t)(v1 ? row1 : 0) * IN_C + qcol;

    float C[8][4];
#pragma unroll
    for (int nt = 0; nt < 8; nt++)
#pragma unroll
        for (int j = 0; j < 4; j++) C[nt][j] = 0.0f;

    const int bbase = qrow * 68 + qcol;

    for (int kc = 0; kc < 4; kc++) {
        const int kc0 = kc * 64;
        __syncthreads();
        // stage W[:, kc0:kc0+64] -> Bs[n][k]
        for (int idx = tid; idx < 64 * 16; idx += 256) {
            int n = idx >> 4;
            int q = idx & 15;
            float4 w = *(const float4*)(W + (size_t)n * IN_C + kc0 + q * 4);
            float* dst = &Bs[n * 68 + q * 4];
            dst[0] = w.x; dst[1] = w.y; dst[2] = w.z; dst[3] = w.w;
        }
        __syncthreads();

#pragma unroll
        for (int k8 = 0; k8 < 64; k8 += 8) {
            const int k0 = kc0 + k8;
            float a0 = v0 ? p0[k0]     : 0.f;
            float a1 = v1 ? p1[k0]     : 0.f;
            float a2 = v0 ? p0[k0 + 4] : 0.f;
            float a3 = v1 ? p1[k0 + 4] : 0.f;
            uint32_t ah[4] = { f2tf(a0), f2tf(a1), f2tf(a2), f2tf(a3) };
            uint32_t al[4] = { f2tf(a0 - uaf(ah[0])), f2tf(a1 - uaf(ah[1])),
                               f2tf(a2 - uaf(ah[2])), f2tf(a3 - uaf(ah[3])) };
#pragma unroll
            for (int nt = 0; nt < 8; nt++) {
                float b0 = Bs[nt * 8 * 68 + bbase + k8];
                float b1 = Bs[nt * 8 * 68 + bbase + k8 + 4];
                uint32_t bh[2] = { f2tf(b0), f2tf(b1) };
                uint32_t bl[2] = { f2tf(b0 - uaf(bh[0])), f2tf(b1 - uaf(bh[1])) };
                mma_tf32(C[nt], ah, bh);   // hi*hi
                mma_tf32(C[nt], ah, bl);   // hi*lo
                mma_tf32(C[nt], al, bh);   // lo*hi
            }
        }
    }

    // epilogue: store h, fused attention scores
    float si0 = 0.f, sj0 = 0.f, si1 = 0.f, sj1 = 0.f;
#pragma unroll
    for (int nt = 0; nt < 8; nt++) {
        int col = nt * 8 + 2 * qcol;
        if (v0) *(float2*)(g_h + (size_t)row0 * OUT_C + col) = make_float2(C[nt][0], C[nt][1]);
        if (v1) *(float2*)(g_h + (size_t)row1 * OUT_C + col) = make_float2(C[nt][2], C[nt][3]);
        si0 += C[nt][0] * sa[col]          + C[nt][1] * sa[col + 1];
        sj0 += C[nt][0] * sa[OUT_C + col]  + C[nt][1] * sa[OUT_C + col + 1];
        si1 += C[nt][2] * sa[col]          + C[nt][3] * sa[col + 1];
        sj1 += C[nt][2] * sa[OUT_C + col]  + C[nt][3] * sa[OUT_C + col + 1];
    }
#pragma unroll
    for (int off = 1; off < 4; off <<= 1) {
        si0 += __shfl_xor_sync(0xffffffffu, si0, off);
        sj0 += __shfl_xor_sync(0xffffffffu, sj0, off);
        si1 += __shfl_xor_sync(0xffffffffu, si1, off);
        sj1 += __shfl_xor_sync(0xffffffffu, sj1, off);
    }
    if (qcol == 0) {
        if (v0) { g_si[row0] = si0; g_sj[row0] = sj0; }
        if (v1) { g_si[row1] = si1; g_sj[row1] = sj1; }
    }
}

// ---------------- kernel: histogram of destinations (real edges only) ----------------
__global__ void hist_kernel(const int* __restrict__ ei) {
    int i = blockIdx.x * blockDim.x + threadIdx.x;
    if (i >= N_EDGES) return;
    atomicAdd(&g_cnt[ei[N_EDGES + i]], 1);
}

// ---------------- scan: counts -> exclusive offsets ----------------
__global__ __launch_bounds__(SCAN_BS) void scan1_kernel() {
    __shared__ int sd[SCAN_BS];
    int tid = threadIdx.x;
    int i   = blockIdx.x * SCAN_BS + tid;
    int v   = (i < N_NODES) ? g_cnt[i] : 0;
    sd[tid] = v;
    __syncthreads();
#pragma unroll
    for (int off = 1; off < SCAN_BS; off <<= 1) {
        int t = (tid >= off) ? sd[tid - off] : 0;
        __syncthreads();
        sd[tid] += t;
        __syncthreads();
    }
    if (i < N_NODES) g_start[i] = sd[tid] - v;
    if (tid == SCAN_BS - 1) g_bsum[blockIdx.x] = sd[tid];
}

__global__ void scan2_kernel() {
    __shared__ int sb[SCAN_NB];
    int tid = threadIdx.x;
    if (tid < SCAN_NB) sb[tid] = g_bsum[tid];
    __syncthreads();
    if (tid == 0) {
        int run = 0;
        for (int b = 0; b < SCAN_NB; b++) { int t = sb[b]; sb[b] = run; run += t; }
    }
    __syncthreads();
    if (tid < SCAN_NB) g_bsum[tid] = sb[tid];
}

__global__ void scan3_kernel() {
    int i = blockIdx.x * blockDim.x + threadIdx.x;
    if (i < N_NODES) {
        int s = g_start[i] + g_bsum[i >> 10];
        g_start[i] = s;
        g_cur[i]   = s;
        if (i == 0) g_start[N_NODES] = NE_TOT;
    }
}

// ---------------- kernel: placement — build CSR entries {row, p} ----------------
__global__ void place_kernel(const int* __restrict__ ei) {
    int i = blockIdx.x * blockDim.x + threadIdx.x;
    if (i >= NE_TOT) return;
    int r, c;
    if (i < N_EDGES) { r = ei[i]; c = ei[N_EDGES + i]; }
    else             { r = c = i - N_EDGES; }
    float e = g_si[c] + g_sj[r];
    e = (e >= 0.f) ? e : NEG_SLOPE * e;
    float p = expf(e);                        // shift-free softmax weight; bounded
    int pos = atomicAdd(&g_cur[c], 1);
    g_csr[pos] = make_float2(__int_as_float(r), p);
}

// ---------------- kernel: warp-per-node fused softmax + aggregate ----------------
__global__ __launch_bounds__(256) void gather_kernel(float* __restrict__ out) {
    int warp = (int)((blockIdx.x * 256 + threadIdx.x) >> 5);
    int lane = threadIdx.x & 31;
    if (warp >= N_NODES) return;

    int s = g_start[warp];
    int e = g_start[warp + 1];

    float acc0 = 0.f, acc1 = 0.f, sp = 0.f;
#pragma unroll 4
    for (int k = s; k < e; k++) {
        float2 t = g_csr[k];                  // uniform within warp
        int   r  = __float_as_int(t.x);
        float p  = t.y;
        sp += p;
        float2 h2 = *(const float2*)(g_h + ((size_t)r << 6) + (lane << 1));
        acc0 = fmaf(p, h2.x, acc0);
        acc1 = fmaf(p, h2.y, acc1);
    }
    float inv = 1.0f / sp;                    // sp > 0: self-loop always present
    float2 o = make_float2(acc0 * inv, acc1 * inv);
    *(float2*)(out + ((size_t)warp << 6) + (lane << 1)) = o;
}

// ---------------- launch ----------------
extern "C" void kernel_launch(void* const* d_in, const int* in_sizes, int n_in,
                              void* d_out, int out_size) {
    const float* x  = (const float*)d_in[0];
    const int*   ei = (const int*)  d_in[1];
    const float* W  = (const float*)d_in[2];
    const float* a  = (const float*)d_in[3];
    float* out = (float*)d_out;

    zero_kernel<<<(N_NODES + 255) / 256, 256>>>();
    gemm_tc_kernel<<<(N_NODES + 127) / 128, 256>>>(x, W, a);
    hist_kernel<<<(N_EDGES + 255) / 256, 256>>>(ei);
    scan1_kernel<<<SCAN_NB, SCAN_BS>>>();
    scan2_kernel<<<1, 128>>>();
    scan3_kernel<<<(N_NODES + 255) / 256, 256>>>();
    place_kernel<<<(NE_TOT + 255) / 256, 256>>>(ei);
    long long gthreads = (long long)N_NODES * 32;
    gather_kernel<<<(unsigned)((gthreads + 255) / 256), 256>>>(out);
}

// round 5
// speedup vs baseline: 2.0749x; 1.3201x over previous
#include <cuda_runtime.h>
#include <math.h>
#include <stdint.h>

#define N_NODES   100000
#define N_EDGES   3200000
#define NE_TOT    (N_EDGES + N_NODES)   // edges + self loops
#define IN_C      256
#define OUT_C     64
#define NEG_SLOPE 0.2f

#define SCAN_BS   1024
#define SCAN_NB   ((N_NODES + SCAN_BS - 1) / SCAN_BS)   // 98

#define GEMM_BLOCKS  782                 // ceil(100000 / 128)
#define HIST_BLOCKS  1568
#define FUSED_BLOCKS (GEMM_BLOCKS + HIST_BLOCKS)

// ---------------- scratch (static device globals; no allocation) ----------------
__device__ float  g_h[(size_t)N_NODES * OUT_C];   // 25.6 MB: h = x @ W^T
__device__ float  g_si[N_NODES];                  // h @ a_i
__device__ float  g_sj[N_NODES];                  // h @ a_j
__device__ int    g_cnt[N_NODES];                 // histogram by col
__device__ int    g_start[N_NODES + 1];           // CSR offsets
__device__ int    g_cur[N_NODES];                 // placement cursors
__device__ int    g_bsum[SCAN_NB];                // block sums for scan
__device__ float2 g_csr[NE_TOT];                  // {row (bitcast), p = exp(e)}

// ---------------- helpers ----------------
// pack two floats into bf16x2 (lower = e, upper = o), and the bf16 residuals
__device__ __forceinline__ void split2(float e, float o, uint32_t& hi, uint32_t& lo) {
    asm("cvt.rn.bf16x2.f32 %0, %1, %2;" : "=r"(hi) : "f"(o), "f"(e));
    float fe = __uint_as_float(hi << 16);
    float fo = __uint_as_float(hi & 0xffff0000u);
    asm("cvt.rn.bf16x2.f32 %0, %1, %2;" : "=r"(lo) : "f"(o - fo), "f"(e - fe));
}

__device__ __forceinline__ void mma_bf16(float* d, const uint32_t* a,
                                         uint32_t b0, uint32_t b1) {
    asm volatile(
        "mma.sync.aligned.m16n8k16.row.col.f32.bf16.bf16.f32 "
        "{%0,%1,%2,%3}, {%4,%5,%6,%7}, {%8,%9}, {%0,%1,%2,%3};"
        : "+f"(d[0]), "+f"(d[1]), "+f"(d[2]), "+f"(d[3])
        : "r"(a[0]), "r"(a[1]), "r"(a[2]), "r"(a[3]), "r"(b0), "r"(b1));
}

// ---------------- kernel: init (self-loop pre-counted in histogram) ----------------
__global__ void zero_kernel() {
    int i = blockIdx.x * blockDim.x + threadIdx.x;
    if (i < N_NODES) g_cnt[i] = 1;
}

// ---------------- fused kernel: bf16-split tensor-core GEMM + scores | histogram ----
// GEMM blocks: 256 thr = 8 warps; warp = 16 rows x 64 cols; block = 128 rows.
// HIST blocks: grid-stride histogram of edge destinations (overlaps with GEMM).
__global__ __launch_bounds__(256) void gemm_hist_kernel(const float* __restrict__ x,
                                                        const float* __restrict__ W,
                                                        const float* __restrict__ a,
                                                        const int* __restrict__ ei) {
    __shared__ uint32_t Bhi[64 * 68];   // W chunk, packed bf16 hi pairs [n][kw]
    __shared__ uint32_t Blo[64 * 68];   // residual bf16 pairs
    __shared__ float sa[2 * OUT_C];

    const int tid = threadIdx.x;

    if (blockIdx.x >= GEMM_BLOCKS) {
        // ---- histogram role ----
        int i = (blockIdx.x - GEMM_BLOCKS) * 256 + tid;
        const int stride = HIST_BLOCKS * 256;
        const int* col = ei + N_EDGES;
        for (; i < N_EDGES; i += stride)
            atomicAdd(&g_cnt[col[i]], 1);
        return;
    }

    // ---- GEMM role ----
    const int warp = tid >> 5;
    const int lane = tid & 31;
    const int qrow = lane >> 2;     // 0..7
    const int qcol = lane & 3;      // 0..3

    if (tid < 2 * OUT_C) sa[tid] = a[tid];

    const int row0 = blockIdx.x * 128 + warp * 16 + qrow;
    const int row1 = row0 + 8;
    const bool v0 = row0 < N_NODES;
    const bool v1 = row1 < N_NODES;
    const float* xr0 = x + (size_t)(v0 ? row0 : 0) * IN_C;
    const float* xr1 = x + (size_t)(v1 ? row1 : 0) * IN_C;

    float C[8][4];
#pragma unroll
    for (int nt = 0; nt < 8; nt++)
#pragma unroll
        for (int j = 0; j < 4; j++) C[nt][j] = 0.0f;

    for (int chunk = 0; chunk < 2; chunk++) {
        const int kbase = chunk * 128;           // floats
        __syncthreads();
        // stage W[:, kbase:kbase+128] as packed bf16 hi/lo, [n][64 words] stride 68
        for (int w = tid; w < 64 * 64; w += 256) {
            int n  = w >> 6;
            int kw = w & 63;
            float2 v = *(const float2*)(W + (size_t)n * IN_C + kbase + kw * 2);
            uint32_t hi, lo;
            split2(v.x, v.y, hi, lo);
            Bhi[n * 68 + kw] = hi;
            Blo[n * 68 + kw] = lo;
        }
        __syncthreads();

#pragma unroll
        for (int s = 0; s < 8; s++) {            // 8 k16-steps per chunk
            const int k0 = kbase + s * 16;
            float2 a00 = *(const float2*)(xr0 + k0 + 2 * qcol);
            float2 a10 = *(const float2*)(xr1 + k0 + 2 * qcol);
            float2 a01 = *(const float2*)(xr0 + k0 + 8 + 2 * qcol);
            float2 a11 = *(const float2*)(xr1 + k0 + 8 + 2 * qcol);
            uint32_t ahi[4], alo[4];
            split2(a00.x, a00.y, ahi[0], alo[0]);   // row0, k-low
            split2(a10.x, a10.y, ahi[1], alo[1]);   // row1, k-low
            split2(a01.x, a01.y, ahi[2], alo[2]);   // row0, k-high
            split2(a11.x, a11.y, ahi[3], alo[3]);   // row1, k-high

            const int bb = qrow * 68 + s * 8 + qcol;
#pragma unroll
            for (int nt = 0; nt < 8; nt++) {
                const int nb = nt * 8 * 68 + bb;
                uint32_t bh0 = Bhi[nb], bh1 = Bhi[nb + 4];
                uint32_t bl0 = Blo[nb], bl1 = Blo[nb + 4];
                mma_bf16(C[nt], ahi, bh0, bh1);     // hi*hi
                mma_bf16(C[nt], ahi, bl0, bl1);     // hi*lo
                mma_bf16(C[nt], alo, bh0, bh1);     // lo*hi
            }
        }
    }

    // epilogue: store h, fused attention scores
    float si0 = 0.f, sj0 = 0.f, si1 = 0.f, sj1 = 0.f;
#pragma unroll
    for (int nt = 0; nt < 8; nt++) {
        int col = nt * 8 + 2 * qcol;
        if (v0) *(float2*)(g_h + (size_t)row0 * OUT_C + col) = make_float2(C[nt][0], C[nt][1]);
        if (v1) *(float2*)(g_h + (size_t)row1 * OUT_C + col) = make_float2(C[nt][2], C[nt][3]);
        si0 += C[nt][0] * sa[col]          + C[nt][1] * sa[col + 1];
        sj0 += C[nt][0] * sa[OUT_C + col]  + C[nt][1] * sa[OUT_C + col + 1];
        si1 += C[nt][2] * sa[col]          + C[nt][3] * sa[col + 1];
        sj1 += C[nt][2] * sa[OUT_C + col]  + C[nt][3] * sa[OUT_C + col + 1];
    }
#pragma unroll
    for (int off = 1; off < 4; off <<= 1) {
        si0 += __shfl_xor_sync(0xffffffffu, si0, off);
        sj0 += __shfl_xor_sync(0xffffffffu, sj0, off);
        si1 += __shfl_xor_sync(0xffffffffu, si1, off);
        sj1 += __shfl_xor_sync(0xffffffffu, sj1, off);
    }
    if (qcol == 0) {
        if (v0) { g_si[row0] = si0; g_sj[row0] = sj0; }
        if (v1) { g_si[row1] = si1; g_sj[row1] = sj1; }
    }
}

// ---------------- scan: counts -> exclusive offsets ----------------
__global__ __launch_bounds__(SCAN_BS) void scan1_kernel() {
    __shared__ int sd[SCAN_BS];
    int tid = threadIdx.x;
    int i   = blockIdx.x * SCAN_BS + tid;
    int v   = (i < N_NODES) ? g_cnt[i] : 0;
    sd[tid] = v;
    __syncthreads();
#pragma unroll
    for (int off = 1; off < SCAN_BS; off <<= 1) {
        int t = (tid >= off) ? sd[tid - off] : 0;
        __syncthreads();
        sd[tid] += t;
        __syncthreads();
    }
    if (i < N_NODES) g_start[i] = sd[tid] - v;
    if (tid == SCAN_BS - 1) g_bsum[blockIdx.x] = sd[tid];
}

__global__ void scan2_kernel() {
    __shared__ int sb[SCAN_NB];
    int tid = threadIdx.x;
    if (tid < SCAN_NB) sb[tid] = g_bsum[tid];
    __syncthreads();
    if (tid == 0) {
        int run = 0;
        for (int b = 0; b < SCAN_NB; b++) { int t = sb[b]; sb[b] = run; run += t; }
    }
    __syncthreads();
    if (tid < SCAN_NB) g_bsum[tid] = sb[tid];
}

__global__ void scan3_kernel() {
    int i = blockIdx.x * blockDim.x + threadIdx.x;
    if (i < N_NODES) {
        int s = g_start[i] + g_bsum[i >> 10];
        g_start[i] = s;
        g_cur[i]   = s;
        if (i == 0) g_start[N_NODES] = NE_TOT;
    }
}

// ---------------- kernel: placement — build CSR entries {row, p} ----------------
__global__ void place_kernel(const int* __restrict__ ei) {
    int i = blockIdx.x * blockDim.x + threadIdx.x;
    if (i >= NE_TOT) return;
    int r, c;
    if (i < N_EDGES) { r = ei[i]; c = ei[N_EDGES + i]; }
    else             { r = c = i - N_EDGES; }
    float e = g_si[c] + g_sj[r];
    e = (e >= 0.f) ? e : NEG_SLOPE * e;
    float p = expf(e);                        // shift-free softmax weight; bounded
    int pos = atomicAdd(&g_cur[c], 1);
    g_csr[pos] = make_float2(__int_as_float(r), p);
}

// ---------------- kernel: warp-per-node fused softmax + aggregate ----------------
__global__ __launch_bounds__(256) void gather_kernel(float* __restrict__ out) {
    int warp = (int)((blockIdx.x * 256 + threadIdx.x) >> 5);
    int lane = threadIdx.x & 31;
    if (warp >= N_NODES) return;

    int s = g_start[warp];
    int e = g_start[warp + 1];

    float acc0 = 0.f, acc1 = 0.f, sp = 0.f;
#pragma unroll 4
    for (int k = s; k < e; k++) {
        float2 t = g_csr[k];                  // uniform within warp
        int   r  = __float_as_int(t.x);
        float p  = t.y;
        sp += p;
        float2 h2 = *(const float2*)(g_h + ((size_t)r << 6) + (lane << 1));
        acc0 = fmaf(p, h2.x, acc0);
        acc1 = fmaf(p, h2.y, acc1);
    }
    float inv = 1.0f / sp;                    // sp > 0: self-loop always present
    float2 o = make_float2(acc0 * inv, acc1 * inv);
    *(float2*)(out + ((size_t)warp << 6) + (lane << 1)) = o;
}

// ---------------- launch ----------------
extern "C" void kernel_launch(void* const* d_in, const int* in_sizes, int n_in,
                              void* d_out, int out_size) {
    const float* x  = (const float*)d_in[0];
    const int*   ei = (const int*)  d_in[1];
    const float* W  = (const float*)d_in[2];
    const float* a  = (const float*)d_in[3];
    float* out = (float*)d_out;

    zero_kernel<<<(N_NODES + 255) / 256, 256>>>();
    gemm_hist_kernel<<<FUSED_BLOCKS, 256>>>(x, W, a, ei);
    scan1_kernel<<<SCAN_NB, SCAN_BS>>>();
    scan2_kernel<<<1, 128>>>();
    scan3_kernel<<<(N_NODES + 255) / 256, 256>>>();
    place_kernel<<<(NE_TOT + 255) / 256, 256>>>(ei);
    long long gthreads = (long long)N_NODES * 32;
    gather_kernel<<<(unsigned)((gthreads + 255) / 256), 256>>>(out);
}